// round 1
// baseline (speedup 1.0000x reference)
#include <cuda_runtime.h>
#include <math.h>

#define BB 16
#define CC 3
#define HH 384
#define WW 1280
#define HW (HH * WW)
#define EPSF 1e-7f

// Per-batch fused transform: coord = d * A @ [x,y,1] + tv   (A = K R K^-1, tv = K t)
__device__ float g_A[BB][9];
__device__ float g_tv[BB][3];

__global__ void precompute_mats(const float* __restrict__ pose,
                                const float* __restrict__ intr) {
    int b = threadIdx.x;
    if (b >= BB) return;

    float K[9];
#pragma unroll
    for (int i = 0; i < 9; i++) K[i] = intr[b * 9 + i];

    // inverse via adjugate
    float c00 =  (K[4] * K[8] - K[5] * K[7]);
    float c01 = -(K[3] * K[8] - K[5] * K[6]);
    float c02 =  (K[3] * K[7] - K[4] * K[6]);
    float det = K[0] * c00 + K[1] * c01 + K[2] * c02;
    float id = 1.0f / det;
    float inv[9];
    inv[0] = c00 * id;
    inv[1] = -(K[1] * K[8] - K[2] * K[7]) * id;
    inv[2] =  (K[1] * K[5] - K[2] * K[4]) * id;
    inv[3] = c01 * id;
    inv[4] =  (K[0] * K[8] - K[2] * K[6]) * id;
    inv[5] = -(K[0] * K[5] - K[2] * K[3]) * id;
    inv[6] = c02 * id;
    inv[7] = -(K[0] * K[7] - K[1] * K[6]) * id;
    inv[8] =  (K[0] * K[4] - K[1] * K[3]) * id;

    // Rodrigues rotation from axis-angle (matches reference: axis = aa/(theta+EPS))
    float ax = pose[b * 6 + 0], ay = pose[b * 6 + 1], az = pose[b * 6 + 2];
    float theta = sqrtf(ax * ax + ay * ay + az * az);
    float ith = 1.0f / (theta + EPSF);
    float x = ax * ith, y = ay * ith, z = az * ith;
    float c = cosf(theta), s = sinf(theta), t = 1.0f - c;
    float R[9];
    R[0] = t * x * x + c;     R[1] = t * x * y - s * z; R[2] = t * z * x + s * y;
    R[3] = t * x * y + s * z; R[4] = t * y * y + c;     R[5] = t * y * z - s * x;
    R[6] = t * z * x - s * y; R[7] = t * y * z + s * x; R[8] = t * z * z + c;

    // A = K * R * invK
    float KR[9];
#pragma unroll
    for (int i = 0; i < 3; i++)
#pragma unroll
        for (int j = 0; j < 3; j++) {
            float sum = 0.0f;
#pragma unroll
            for (int k = 0; k < 3; k++) sum += K[i * 3 + k] * R[k * 3 + j];
            KR[i * 3 + j] = sum;
        }
#pragma unroll
    for (int i = 0; i < 3; i++)
#pragma unroll
        for (int j = 0; j < 3; j++) {
            float sum = 0.0f;
#pragma unroll
            for (int k = 0; k < 3; k++) sum += KR[i * 3 + k] * inv[k * 3 + j];
            g_A[b][i * 3 + j] = sum;
        }

    // tv = K * t
    float tx = pose[b * 6 + 3], ty = pose[b * 6 + 4], tz = pose[b * 6 + 5];
    g_tv[b][0] = K[0] * tx + K[1] * ty + K[2] * tz;
    g_tv[b][1] = K[3] * tx + K[4] * ty + K[5] * tz;
    g_tv[b][2] = K[6] * tx + K[7] * ty + K[8] * tz;
}

__global__ void __launch_bounds__(256)
warp_sample_kernel(const float* __restrict__ img,
                   const float* __restrict__ depth,
                   float* __restrict__ out) {
    int idx = blockIdx.x * blockDim.x + threadIdx.x;
    if (idx >= BB * HW) return;

    int b = idx / HW;
    int rem = idx - b * HW;
    int h = rem / WW;
    int w = rem - h * WW;

    float d = depth[idx];

    // per-batch coefficients (block lies entirely within one batch -> L1 broadcast)
    float a0 = g_A[b][0], a1 = g_A[b][1], a2 = g_A[b][2];
    float a3 = g_A[b][3], a4 = g_A[b][4], a5 = g_A[b][5];
    float a6 = g_A[b][6], a7 = g_A[b][7], a8 = g_A[b][8];
    float t0 = g_tv[b][0], t1 = g_tv[b][1], t2 = g_tv[b][2];

    float fx = (float)w, fy = (float)h;
    float X = d * (a0 * fx + a1 * fy + a2) + t0;
    float Y = d * (a3 * fx + a4 * fy + a5) + t1;
    float Z = d * (a6 * fx + a7 * fy + a8) + t2 + EPSF;

    float px = X / Z;
    float py = Y / Z;

    // replicate the reference's normalize/denormalize roundtrip
    float gx = px / (float)(WW - 1) * 2.0f - 1.0f;
    float gy = py / (float)(HH - 1) * 2.0f - 1.0f;
    float xs = (gx + 1.0f) * 0.5f * (float)(WW - 1);
    float ys = (gy + 1.0f) * 0.5f * (float)(HH - 1);

    float x0f = floorf(xs), y0f = floorf(ys);
    float x1f = x0f + 1.0f, y1f = y0f + 1.0f;
    float wx1 = xs - x0f, wx0 = 1.0f - wx1;
    float wy1 = ys - y0f, wy0 = 1.0f - wy1;

    // in-bounds masks on the UNCLIPPED coordinates (reference semantics)
    float ib_x0 = (x0f >= 0.0f && x0f <= (float)(WW - 1)) ? 1.0f : 0.0f;
    float ib_x1 = (x1f >= 0.0f && x1f <= (float)(WW - 1)) ? 1.0f : 0.0f;
    float ib_y0 = (y0f >= 0.0f && y0f <= (float)(HH - 1)) ? 1.0f : 0.0f;
    float ib_y1 = (y1f >= 0.0f && y1f <= (float)(HH - 1)) ? 1.0f : 0.0f;

    // clamp, then gather
    int xc0 = (int)fminf(fmaxf(x0f, 0.0f), (float)(WW - 1));
    int xc1 = (int)fminf(fmaxf(x1f, 0.0f), (float)(WW - 1));
    int yc0 = (int)fminf(fmaxf(y0f, 0.0f), (float)(HH - 1));
    int yc1 = (int)fminf(fmaxf(y1f, 0.0f), (float)(HH - 1));

    float w00 = wx0 * wy0 * ib_x0 * ib_y0;
    float w10 = wx1 * wy0 * ib_x1 * ib_y0;
    float w01 = wx0 * wy1 * ib_x0 * ib_y1;
    float w11 = wx1 * wy1 * ib_x1 * ib_y1;

    int i00 = yc0 * WW + xc0;
    int i10 = yc0 * WW + xc1;
    int i01 = yc1 * WW + xc0;
    int i11 = yc1 * WW + xc1;

    int base = b * CC * HW;
#pragma unroll
    for (int c = 0; c < CC; c++) {
        const float* p = img + base + c * HW;
        float v = w00 * __ldg(p + i00) + w10 * __ldg(p + i10) +
                  w01 * __ldg(p + i01) + w11 * __ldg(p + i11);
        out[base + c * HW + rem] = v;
    }
}

extern "C" void kernel_launch(void* const* d_in, const int* in_sizes, int n_in,
                              void* d_out, int out_size) {
    const float* source_image = (const float*)d_in[0];
    const float* depth_map    = (const float*)d_in[1];
    const float* pose         = (const float*)d_in[2];
    const float* intrinsic    = (const float*)d_in[3];
    float* out = (float*)d_out;

    precompute_mats<<<1, 32>>>(pose, intrinsic);

    const int total = BB * HW;
    const int threads = 256;
    const int blocks = (total + threads - 1) / threads;
    warp_sample_kernel<<<blocks, threads>>>(source_image, depth_map, out);
}